// round 13
// baseline (speedup 1.0000x reference)
#include <cuda_runtime.h>
#include <cuda_bf16.h>
#include <cstdint>

#define BN_EPS_F 1e-5f
#define ATT_SCALE 0.125f   // 64^-0.5

// packed f32x2 FMA: d = a*b + d  (Blackwell sm_100+/sm_103a)
union F2LL { float2 f; unsigned long long u; };
__device__ __forceinline__ void fma2(float2& d, float2 a, float2 b) {
    F2LL D, A, B; D.f = d; A.f = a; B.f = b;
    asm("fma.rn.f32x2 %0, %1, %2, %0;" : "+l"(D.u) : "l"(A.u), "l"(B.u));
    d = D.f;
}

// ---------------------------------------------------------------------------
// Attention branch. One block per (batch b, head h in [0,4)).
// 256 threads; thread i owns query row i.
//   xb[b,n,s] = relu(a[n]*x[b,n,s] + c[n]),  a = gamma*rsqrt(var+eps), c = beta - mean*a
//   scores[i,j] = SCALE*wq[i]*wk[j] * dot_d(xb[b,i,64h+d], xb[b,j,64h+d])
//   out[i,d]    = sum_j softmax_j(scores)[i,j] * wv[j] * xb[b,j,64h+d]
//   output[b,i,32h+u] = 0.5*(out[i,2u]+out[i,2u+1])
// Scores are O(1) -> exp without max subtraction is safe.
// ---------------------------------------------------------------------------
__global__ __launch_bounds__(256, 1)
void attn_kernel(const float* __restrict__ x,
                 const float* __restrict__ bn_gamma, const float* __restrict__ bn_beta,
                 const float* __restrict__ bn_mean,  const float* __restrict__ bn_var,
                 const float* __restrict__ w_qkv,
                 float* __restrict__ out)
{
    extern __shared__ float smem[];
    float4* Xsh = reinterpret_cast<float4*>(smem);   // [256][16] float4 = 64 KB
    float*  wk_s = smem + 256 * 64;                  // [256]
    float*  wv_s = wk_s + 256;                       // [256]

    const int b = blockIdx.x >> 2;
    const int h = blockIdx.x & 3;
    const int i = threadIdx.x;

    const float* xrow = x + ((size_t)b * 256 + i) * 256 + h * 64;

    const float a  = bn_gamma[i] * rsqrtf(bn_var[i] + BN_EPS_F);
    const float c  = bn_beta[i] - bn_mean[i] * a;

    float4 xi[16];
#pragma unroll
    for (int t = 0; t < 16; t++) {
        float4 v = reinterpret_cast<const float4*>(xrow)[t];
        v.x = fmaxf(fmaf(v.x, a, c), 0.f);
        v.y = fmaxf(fmaf(v.y, a, c), 0.f);
        v.z = fmaxf(fmaf(v.z, a, c), 0.f);
        v.w = fmaxf(fmaf(v.w, a, c), 0.f);
        xi[t] = v;
        Xsh[i * 16 + t] = v;
    }
    const float wq = w_qkv[i * 6 + 0];
    wk_s[i] = w_qkv[i * 6 + 2];
    wv_s[i] = w_qkv[i * 6 + 4];
    __syncthreads();

    const float cw = ATT_SCALE * wq;
    float  l = 0.f;
    float2 acc[32];
#pragma unroll
    for (int t = 0; t < 32; t++) acc[t] = make_float2(0.f, 0.f);

    for (int j = 0; j < 256; j++) {
        const float4* Xj = &Xsh[j * 16];
        float2 d0 = make_float2(0.f, 0.f);
        float2 d1 = make_float2(0.f, 0.f);
#pragma unroll
        for (int t = 0; t < 16; t++) {
            float4 v = Xj[t];
            float4 u = xi[t];
            fma2(d0, make_float2(u.x, u.y), make_float2(v.x, v.y));
            fma2(d1, make_float2(u.z, u.w), make_float2(v.z, v.w));
        }
        float s = (d0.x + d0.y + d1.x + d1.y) * (cw * wk_s[j]);
        float p = __expf(s);
        l += p;
        float  pv  = p * wv_s[j];
        float2 pv2 = make_float2(pv, pv);
#pragma unroll
        for (int t = 0; t < 16; t++) {
            float4 v = Xj[t];
            fma2(acc[2 * t + 0], pv2, make_float2(v.x, v.y));
            fma2(acc[2 * t + 1], pv2, make_float2(v.z, v.w));
        }
    }

    const float inv = 0.5f / l;
    float4* orow = reinterpret_cast<float4*>(out + ((size_t)b * 256 + i) * 256 + h * 32);
#pragma unroll
    for (int t = 0; t < 8; t++) {
        float4 o;
        o.x = (acc[4 * t + 0].x + acc[4 * t + 0].y) * inv;
        o.y = (acc[4 * t + 1].x + acc[4 * t + 1].y) * inv;
        o.z = (acc[4 * t + 2].x + acc[4 * t + 2].y) * inv;
        o.w = (acc[4 * t + 3].x + acc[4 * t + 3].y) * inv;
        orow[t] = o;
    }
}

// ---------------------------------------------------------------------------
// Conv branch (heads 4..7, q2:1x3 conv, k2:3x1 conv, +v2; pairs averaged).
// Thread = (n2 channel, ph row). For channel c2=n2 (h'=n2>>6, m=n2&63),
// spatial row r uses xb row n_r = 4m + (r>>2), cols [64h' + 16(r&3), +16).
//   q2[r,pw]=T_r[pw]*wq2(n_r) (only mid row needed)
//   k2[r,pw]=T_r[pw]*wk2(n_r)
//   res[pw] = conv1x3(q2)[pw] + conv3x1(k2)[pw] + T_mid[pw]*wv2(n_mid)
//   output[b,n2,128+8*ph+u] = 0.5*(res[2u]+res[2u+1])
// ---------------------------------------------------------------------------
__global__ __launch_bounds__(256)
void conv_kernel(const float* __restrict__ x,
                 const float* __restrict__ bn_gamma, const float* __restrict__ bn_beta,
                 const float* __restrict__ bn_mean,  const float* __restrict__ bn_var,
                 const float* __restrict__ w_qkv,
                 const float* __restrict__ w_qs, const float* __restrict__ w_ks,
                 float* __restrict__ out)
{
    const int tid = threadIdx.x;
    const int b   = blockIdx.x >> 4;
    const int n2  = ((blockIdx.x & 15) << 4) | (tid >> 4);
    const int ph  = tid & 15;
    const int hp  = n2 >> 6;
    const int m   = n2 & 63;

    float Tm1[16], T0[16], Tp1[16];
#pragma unroll
    for (int t = 0; t < 16; t++) { Tm1[t] = 0.f; Tp1[t] = 0.f; }

    auto loadrow = [&](int r, float* T) -> int {
        int nr = (m << 2) + (r >> 2);
        int cb = (hp << 6) + ((r & 3) << 4);
        float a = bn_gamma[nr] * rsqrtf(bn_var[nr] + BN_EPS_F);
        float c = bn_beta[nr] - bn_mean[nr] * a;
        const float4* p = reinterpret_cast<const float4*>(
            x + ((size_t)b * 256 + nr) * 256 + cb);
#pragma unroll
        for (int t = 0; t < 4; t++) {
            float4 v = p[t];
            T[4 * t + 0] = fmaxf(fmaf(v.x, a, c), 0.f);
            T[4 * t + 1] = fmaxf(fmaf(v.y, a, c), 0.f);
            T[4 * t + 2] = fmaxf(fmaf(v.z, a, c), 0.f);
            T[4 * t + 3] = fmaxf(fmaf(v.w, a, c), 0.f);
        }
        return nr;
    };

    const bool has_m1 = (ph > 0);
    const bool has_p1 = (ph < 15);
    int n_m1 = has_m1 ? loadrow(ph - 1, Tm1) : 0;
    int n_0  = loadrow(ph, T0);
    int n_p1 = has_p1 ? loadrow(ph + 1, Tp1) : 0;

    const float wq2 = w_qkv[n_0 * 6 + 1];
    const float wv2 = w_qkv[n_0 * 6 + 5];
    const float wk0 = w_qkv[n_0 * 6 + 3];
    const float wkm = has_m1 ? w_qkv[n_m1 * 6 + 3] : 0.f;
    const float wkp = has_p1 ? w_qkv[n_p1 * 6 + 3] : 0.f;

    const float qs0 = w_qs[n2 * 3 + 0], qs1 = w_qs[n2 * 3 + 1], qs2 = w_qs[n2 * 3 + 2];
    const float ks0 = w_ks[n2 * 3 + 0], ks1 = w_ks[n2 * 3 + 1], ks2 = w_ks[n2 * 3 + 2];

    // fold wk into row weights for the 3x1 conv
    const float km = wkm * ks0, k0 = wk0 * ks1, kp = wkp * ks2;

    float q[16], res[16];
#pragma unroll
    for (int pw = 0; pw < 16; pw++) q[pw] = T0[pw] * wq2;

#pragma unroll
    for (int pw = 0; pw < 16; pw++) {
        float cq = q[pw] * qs1;
        if (pw > 0)  cq = fmaf(q[pw - 1], qs0, cq);
        if (pw < 15) cq = fmaf(q[pw + 1], qs2, cq);
        float ck = fmaf(Tm1[pw], km, fmaf(Tp1[pw], kp, T0[pw] * k0));
        res[pw] = cq + ck + T0[pw] * wv2;
    }

    float* orow = out + ((size_t)b * 256 + n2) * 256 + 128 + ph * 8;
#pragma unroll
    for (int u = 0; u < 8; u++)
        orow[u] = 0.5f * (res[2 * u] + res[2 * u + 1]);
}

extern "C" void kernel_launch(void* const* d_in, const int* in_sizes, int n_in,
                              void* d_out, int out_size)
{
    const float* x    = (const float*)d_in[0];
    const float* g    = (const float*)d_in[1];
    const float* be   = (const float*)d_in[2];
    const float* mu   = (const float*)d_in[3];
    const float* var  = (const float*)d_in[4];
    const float* wqkv = (const float*)d_in[5];
    const float* wqs  = (const float*)d_in[6];
    const float* wks  = (const float*)d_in[7];
    float* out = (float*)d_out;

    const int B = in_sizes[0] / (256 * 256);   // 128

    const int smem_bytes = 256 * 64 * 4 + 2 * 256 * 4;  // 67584
    cudaFuncSetAttribute(attn_kernel, cudaFuncAttributeMaxDynamicSharedMemorySize,
                         smem_bytes);

    attn_kernel<<<B * 4, 256, smem_bytes>>>(x, g, be, mu, var, wqkv, out);
    conv_kernel<<<B * 16, 256>>>(x, g, be, mu, var, wqkv, wqs, wks, out);
}

// round 14
// speedup vs baseline: 1.0061x; 1.0061x over previous
#include <cuda_runtime.h>
#include <cuda_bf16.h>
#include <cstdint>

#define BN_EPS_F 1e-5f
#define ATT_SCALE 0.125f   // 64^-0.5

// packed f32x2 FMA: d = a*b + d  (Blackwell sm_100+/sm_103a)
union F2LL { float2 f; unsigned long long u; };
__device__ __forceinline__ void fma2(float2& d, float2 a, float2 b) {
    F2LL D, A, B; D.f = d; A.f = a; B.f = b;
    asm("fma.rn.f32x2 %0, %1, %2, %0;" : "+l"(D.u) : "l"(A.u), "l"(B.u));
    d = D.f;
}

// ---------------------------------------------------------------------------
// Attention branch. One block per (batch b, head h in [0,4)).
// 256 threads; thread i owns query row i.
//   xb[b,n,s] = relu(a[n]*x[b,n,s] + c[n]),  a = gamma*rsqrt(var+eps), c = beta - mean*a
//   scores[i,j] = SCALE*wq[i]*wk[j] * dot_d(xb[b,i,64h+d], xb[b,j,64h+d])
//   out[i,d]    = sum_j softmax_j(scores)[i,j] * wv[j] * xb[b,j,64h+d]
//   output[b,i,32h+u] = 0.5*(out[i,2u]+out[i,2u+1])
// Scores are O(1) -> exp without max subtraction is safe.
// ---------------------------------------------------------------------------
__global__ __launch_bounds__(256, 1)
void attn_kernel(const float* __restrict__ x,
                 const float* __restrict__ bn_gamma, const float* __restrict__ bn_beta,
                 const float* __restrict__ bn_mean,  const float* __restrict__ bn_var,
                 const float* __restrict__ w_qkv,
                 float* __restrict__ out)
{
    extern __shared__ float smem[];
    float4* Xsh = reinterpret_cast<float4*>(smem);   // [256][16] float4 = 64 KB
    float*  wk_s = smem + 256 * 64;                  // [256]
    float*  wv_s = wk_s + 256;                       // [256]

    const int b = blockIdx.x >> 2;
    const int h = blockIdx.x & 3;
    const int i = threadIdx.x;

    const float* xrow = x + ((size_t)b * 256 + i) * 256 + h * 64;

    const float a  = bn_gamma[i] * rsqrtf(bn_var[i] + BN_EPS_F);
    const float c  = bn_beta[i] - bn_mean[i] * a;

    float4 xi[16];
#pragma unroll
    for (int t = 0; t < 16; t++) {
        float4 v = reinterpret_cast<const float4*>(xrow)[t];
        v.x = fmaxf(fmaf(v.x, a, c), 0.f);
        v.y = fmaxf(fmaf(v.y, a, c), 0.f);
        v.z = fmaxf(fmaf(v.z, a, c), 0.f);
        v.w = fmaxf(fmaf(v.w, a, c), 0.f);
        xi[t] = v;
        Xsh[i * 16 + t] = v;
    }
    const float wq = w_qkv[i * 6 + 0];
    wk_s[i] = w_qkv[i * 6 + 2];
    wv_s[i] = w_qkv[i * 6 + 4];
    __syncthreads();

    const float cw = ATT_SCALE * wq;
    float  l = 0.f;
    float2 acc[32];
#pragma unroll
    for (int t = 0; t < 32; t++) acc[t] = make_float2(0.f, 0.f);

    for (int j = 0; j < 256; j++) {
        const float4* Xj = &Xsh[j * 16];
        float2 d0 = make_float2(0.f, 0.f);
        float2 d1 = make_float2(0.f, 0.f);
#pragma unroll
        for (int t = 0; t < 16; t++) {
            float4 v = Xj[t];
            float4 u = xi[t];
            fma2(d0, make_float2(u.x, u.y), make_float2(v.x, v.y));
            fma2(d1, make_float2(u.z, u.w), make_float2(v.z, v.w));
        }
        float s = (d0.x + d0.y + d1.x + d1.y) * (cw * wk_s[j]);
        float p = __expf(s);
        l += p;
        float  pv  = p * wv_s[j];
        float2 pv2 = make_float2(pv, pv);
#pragma unroll
        for (int t = 0; t < 16; t++) {
            float4 v = Xj[t];
            fma2(acc[2 * t + 0], pv2, make_float2(v.x, v.y));
            fma2(acc[2 * t + 1], pv2, make_float2(v.z, v.w));
        }
    }

    const float inv = 0.5f / l;
    float4* orow = reinterpret_cast<float4*>(out + ((size_t)b * 256 + i) * 256 + h * 32);
#pragma unroll
    for (int t = 0; t < 8; t++) {
        float4 o;
        o.x = (acc[4 * t + 0].x + acc[4 * t + 0].y) * inv;
        o.y = (acc[4 * t + 1].x + acc[4 * t + 1].y) * inv;
        o.z = (acc[4 * t + 2].x + acc[4 * t + 2].y) * inv;
        o.w = (acc[4 * t + 3].x + acc[4 * t + 3].y) * inv;
        orow[t] = o;
    }
}

// ---------------------------------------------------------------------------
// Conv branch (heads 4..7, q2:1x3 conv, k2:3x1 conv, +v2; pairs averaged).
// Thread = (n2 channel, ph row). For channel c2=n2 (h'=n2>>6, m=n2&63),
// spatial row r uses xb row n_r = 4m + (r>>2), cols [64h' + 16(r&3), +16).
//   q2[r,pw]=T_r[pw]*wq2(n_r) (only mid row needed)
//   k2[r,pw]=T_r[pw]*wk2(n_r)
//   res[pw] = conv1x3(q2)[pw] + conv3x1(k2)[pw] + T_mid[pw]*wv2(n_mid)
//   output[b,n2,128+8*ph+u] = 0.5*(res[2u]+res[2u+1])
// ---------------------------------------------------------------------------
__global__ __launch_bounds__(256)
void conv_kernel(const float* __restrict__ x,
                 const float* __restrict__ bn_gamma, const float* __restrict__ bn_beta,
                 const float* __restrict__ bn_mean,  const float* __restrict__ bn_var,
                 const float* __restrict__ w_qkv,
                 const float* __restrict__ w_qs, const float* __restrict__ w_ks,
                 float* __restrict__ out)
{
    const int tid = threadIdx.x;
    const int b   = blockIdx.x >> 4;
    const int n2  = ((blockIdx.x & 15) << 4) | (tid >> 4);
    const int ph  = tid & 15;
    const int hp  = n2 >> 6;
    const int m   = n2 & 63;

    float Tm1[16], T0[16], Tp1[16];
#pragma unroll
    for (int t = 0; t < 16; t++) { Tm1[t] = 0.f; Tp1[t] = 0.f; }

    auto loadrow = [&](int r, float* T) -> int {
        int nr = (m << 2) + (r >> 2);
        int cb = (hp << 6) + ((r & 3) << 4);
        float a = bn_gamma[nr] * rsqrtf(bn_var[nr] + BN_EPS_F);
        float c = bn_beta[nr] - bn_mean[nr] * a;
        const float4* p = reinterpret_cast<const float4*>(
            x + ((size_t)b * 256 + nr) * 256 + cb);
#pragma unroll
        for (int t = 0; t < 4; t++) {
            float4 v = p[t];
            T[4 * t + 0] = fmaxf(fmaf(v.x, a, c), 0.f);
            T[4 * t + 1] = fmaxf(fmaf(v.y, a, c), 0.f);
            T[4 * t + 2] = fmaxf(fmaf(v.z, a, c), 0.f);
            T[4 * t + 3] = fmaxf(fmaf(v.w, a, c), 0.f);
        }
        return nr;
    };

    const bool has_m1 = (ph > 0);
    const bool has_p1 = (ph < 15);
    int n_m1 = has_m1 ? loadrow(ph - 1, Tm1) : 0;
    int n_0  = loadrow(ph, T0);
    int n_p1 = has_p1 ? loadrow(ph + 1, Tp1) : 0;

    const float wq2 = w_qkv[n_0 * 6 + 1];
    const float wv2 = w_qkv[n_0 * 6 + 5];
    const float wk0 = w_qkv[n_0 * 6 + 3];
    const float wkm = has_m1 ? w_qkv[n_m1 * 6 + 3] : 0.f;
    const float wkp = has_p1 ? w_qkv[n_p1 * 6 + 3] : 0.f;

    const float qs0 = w_qs[n2 * 3 + 0], qs1 = w_qs[n2 * 3 + 1], qs2 = w_qs[n2 * 3 + 2];
    const float ks0 = w_ks[n2 * 3 + 0], ks1 = w_ks[n2 * 3 + 1], ks2 = w_ks[n2 * 3 + 2];

    // fold wk into row weights for the 3x1 conv
    const float km = wkm * ks0, k0 = wk0 * ks1, kp = wkp * ks2;

    float q[16], res[16];
#pragma unroll
    for (int pw = 0; pw < 16; pw++) q[pw] = T0[pw] * wq2;

#pragma unroll
    for (int pw = 0; pw < 16; pw++) {
        float cq = q[pw] * qs1;
        if (pw > 0)  cq = fmaf(q[pw - 1], qs0, cq);
        if (pw < 15) cq = fmaf(q[pw + 1], qs2, cq);
        float ck = fmaf(Tm1[pw], km, fmaf(Tp1[pw], kp, T0[pw] * k0));
        res[pw] = cq + ck + T0[pw] * wv2;
    }

    float* orow = out + ((size_t)b * 256 + n2) * 256 + 128 + ph * 8;
#pragma unroll
    for (int u = 0; u < 8; u++)
        orow[u] = 0.5f * (res[2 * u] + res[2 * u + 1]);
}

extern "C" void kernel_launch(void* const* d_in, const int* in_sizes, int n_in,
                              void* d_out, int out_size)
{
    const float* x    = (const float*)d_in[0];
    const float* g    = (const float*)d_in[1];
    const float* be   = (const float*)d_in[2];
    const float* mu   = (const float*)d_in[3];
    const float* var  = (const float*)d_in[4];
    const float* wqkv = (const float*)d_in[5];
    const float* wqs  = (const float*)d_in[6];
    const float* wks  = (const float*)d_in[7];
    float* out = (float*)d_out;

    const int B = in_sizes[0] / (256 * 256);   // 128

    const int smem_bytes = 256 * 64 * 4 + 2 * 256 * 4;  // 67584
    cudaFuncSetAttribute(attn_kernel, cudaFuncAttributeMaxDynamicSharedMemorySize,
                         smem_bytes);

    attn_kernel<<<B * 4, 256, smem_bytes>>>(x, g, be, mu, var, wqkv, out);
    conv_kernel<<<B * 16, 256>>>(x, g, be, mu, var, wqkv, wqs, wks, out);
}